// round 12
// baseline (speedup 1.0000x reference)
#include <cuda_runtime.h>
#include <cstdint>

typedef unsigned long long ull;

#define NB 2
#define CH 64
#define DS 64
#define VOL (DS*DS*DS)
#define CH_SHIFT 18
#define TOTAL (NB*CH*VOL)

__device__ float  g_t0[TOTAL];
__device__ float  g_t1[TOTAL];
__device__ float2 g_part[64*64];
__device__ float  g_A[CH], g_B0[CH], g_PAD[CH], g_BS[CH], g_B1[CH];
__device__ ull    g_w1p[4096];

// ---------------------------------------------------------------------------
__device__ __forceinline__ ull pk2(float a, float b) {
    ull r;
    asm("mov.b64 %0, {%1, %2};" : "=l"(r) : "f"(a), "f"(b));
    return r;
}
__device__ __forceinline__ void unpk2(ull v, float& lo, float& hi) {
    asm("mov.b64 {%0, %1}, %2;" : "=f"(lo), "=f"(hi) : "l"(v));
}
__device__ __forceinline__ void fma2(ull& d, ull a, ull b) {
    asm("fma.rn.f32x2 %0, %1, %2, %0;" : "+l"(d) : "l"(a), "l"(b));
}

// ---------------------------------------------------------------------------
// K1: per-channel partial sums.
// ---------------------------------------------------------------------------
__global__ __launch_bounds__(256) void k1_stats(const float* __restrict__ x) {
    int b = blockIdx.x, c = blockIdx.y;
    int n = b >> 5, chunk = b & 31;
    size_t base = ((size_t)((n << 6) + c) << CH_SHIFT) + ((size_t)chunk << 13);
    const float4* p = (const float4*)(x + base);
    float s = 0.f, q = 0.f;
    #pragma unroll
    for (int it = 0; it < 8; ++it) {
        float4 v = p[(it << 8) + threadIdx.x];
        s += v.x + v.y + v.z + v.w;
        q += v.x*v.x + v.y*v.y + v.z*v.z + v.w*v.w;
    }
    #pragma unroll
    for (int o = 16; o; o >>= 1) {
        s += __shfl_down_sync(0xffffffffu, s, o);
        q += __shfl_down_sync(0xffffffffu, q, o);
    }
    __shared__ float ss[8], qq[8];
    int w = threadIdx.x >> 5, l = threadIdx.x & 31;
    if (l == 0) { ss[w] = s; qq[w] = q; }
    __syncthreads();
    if (threadIdx.x == 0) {
        float S = 0.f, Q = 0.f;
        #pragma unroll
        for (int i = 0; i < 8; ++i) { S += ss[i]; Q += qq[i]; }
        g_part[(c << 6) + b] = make_float2(S, Q);
    }
}

__global__ void k1_final(const float* __restrict__ v0, const float* __restrict__ v1,
                         const float* __restrict__ v2, const float* __restrict__ v3,
                         const float* __restrict__ v4, const float* __restrict__ w0) {
    int c = threadIdx.x;
    if (c >= CH) return;
    const float* vs[5] = {v0, v1, v2, v3, v4};
    float sums[5];
    for (int i = 0; i < 5; ++i) {
        float s = 0.f;
        for (int j = 0; j < CH; ++j) s += vs[i][j];
        sums[i] = s;
    }
    int gi = -1, ok = 1;
    for (int i = 0; i < 5; ++i) {
        if (fabsf(sums[i] - 64.f) < 1.f) { if (gi < 0) gi = i; else ok = 0; }
        else if (fabsf(sums[i]) > 1.f) ok = 0;
    }
    if (!ok || gi < 0) gi = 0;
    const float* gamma = vs[gi];
    const float* rest[4]; int r = 0;
    for (int i = 0; i < 5; ++i) if (i != gi) rest[r++] = vs[i];
    const float* beta = rest[0];
    const float* b0   = rest[1];
    const float* bs   = rest[2];
    const float* b1   = rest[3];

    float S = 0.f, Q = 0.f;
    for (int b = 0; b < 64; ++b) { float2 p = g_part[(c << 6) + b]; S += p.x; Q += p.y; }
    const float inv = 1.0f / (float)(NB * VOL);
    float mean = S * inv;
    float var = fmaf(Q, inv, -mean * mean);
    if (var < 0.f) var = 0.f;
    float a = gamma[c] * rsqrtf(var + 1e-5f);
    float e = beta[c] - mean * a;
    float s0 = 0.f;
    for (int t = 0; t < 125; ++t) s0 += w0[c * 125 + t];
    g_A[c]   = a;
    g_B0[c]  = fmaf(e, s0, b0[c]);
    g_PAD[c] = (a != 0.0f) ? (-e / a) : 0.0f;
    g_BS[c]  = bs[c];
    g_B1[c]  = b1[c];
}

__global__ void k4_packw(const float* __restrict__ w1) {
    int i = blockIdx.x * 256 + threadIdx.x;
    if (i < 4096) { float w = w1[i]; g_w1p[i] = pk2(w, w); }
}

// ---------------------------------------------------------------------------
// K2: depthwise 5x5x5 conv (pad 2), BN folded. Zero-pack f32x2.
// Vectorized: data rows 3x LDS.128, weight rows padded to 6 ull (2x LDS.128 +
// 1x LDS.64). Thread: 2 d-planes x 8 w outputs. 4 blocks/SM.
// ---------------------------------------------------------------------------
__global__ __launch_bounds__(256, 4) void k2_conv5(const float* __restrict__ x,
                                                   const float* __restrict__ w0) {
    __shared__ float sm[12 * 12 * 68];
    __shared__ ull w2s[150];                 // 25 rows x 6 (5 taps + pad)
    int c = blockIdx.y, n = blockIdx.z;
    int dt = (blockIdx.x >> 3) << 3;
    int ht = (blockIdx.x & 7) << 3;
    int tid = threadIdx.x;
    size_t base = ((size_t)((n << 6) + c) << CH_SHIFT);

    float pad = g_PAD[c];
    if (tid < 150) {
        int row = tid / 6, lane = tid % 6;
        float w = (lane < 5) ? w0[c * 125 + row * 5 + lane] : 0.f;
        w2s[tid] = pk2(w, w);
    }
    for (int i = tid; i < 12 * 12 * 68; i += 256) {
        int wx = i % 68; int t = i / 68; int hy = t % 12; int dz = t / 12;
        int d = dt + dz - 2, h = ht + hy - 2, w = wx - 2;
        float v = pad;
        if ((unsigned)d < 64u && (unsigned)h < 64u && (unsigned)w < 64u)
            v = x[base + ((size_t)d << 12) + (h << 6) + w];
        sm[i] = v;
    }
    __syncthreads();

    int wg = tid & 7;
    int hl = (tid >> 3) & 7;
    int pp = tid >> 6;
    int wbase = wg << 3;

    ull aA0[4], aB0[5], aA1[4], aB1[5];
    #pragma unroll
    for (int i = 0; i < 4; ++i) { aA0[i] = 0ull; aA1[i] = 0ull; }
    #pragma unroll
    for (int i = 0; i < 5; ++i) { aB0[i] = 0ull; aB1[i] = 0ull; }

    #pragma unroll 1
    for (int kdp = 0; kdp < 6; ++kdp) {
        int z = (pp << 1) + kdp;
        const ull* zrow = (const ull*)&sm[(z * 12 + hl) * 68 + wbase];
        #pragma unroll 1
        for (int kh = 0; kh < 5; ++kh) {
            const ull* rp = zrow + kh * 34;
            ulonglong2 d01 = *(const ulonglong2*)(rp);
            ulonglong2 d23 = *(const ulonglong2*)(rp + 2);
            ulonglong2 d45 = *(const ulonglong2*)(rp + 4);
            ull re[6] = {d01.x, d01.y, d23.x, d23.y, d45.x, d45.y};
            if (kdp < 5) {
                const ull* wp = &w2s[(kdp * 5 + kh) * 6];
                ulonglong2 wA = *(const ulonglong2*)wp;
                ulonglong2 wB = *(const ulonglong2*)(wp + 2);
                ull w4 = wp[4];
                ull we[3] = {wA.x, wB.x, w4};
                ull wo[2] = {wA.y, wB.y};
                #pragma unroll
                for (int e = 0; e < 3; ++e)
                    #pragma unroll
                    for (int i = 0; i < 4; ++i) fma2(aA0[i], we[e], re[i + e]);
                #pragma unroll
                for (int o = 0; o < 2; ++o)
                    #pragma unroll
                    for (int j = 0; j < 5; ++j) fma2(aB0[j], wo[o], re[j + o]);
            }
            if (kdp >= 1) {
                const ull* wp = &w2s[((kdp - 1) * 5 + kh) * 6];
                ulonglong2 wA = *(const ulonglong2*)wp;
                ulonglong2 wB = *(const ulonglong2*)(wp + 2);
                ull w4 = wp[4];
                ull we[3] = {wA.x, wB.x, w4};
                ull wo[2] = {wA.y, wB.y};
                #pragma unroll
                for (int e = 0; e < 3; ++e)
                    #pragma unroll
                    for (int i = 0; i < 4; ++i) fma2(aA1[i], we[e], re[i + e]);
                #pragma unroll
                for (int o = 0; o < 2; ++o)
                    #pragma unroll
                    for (int j = 0; j < 5; ++j) fma2(aB1[j], wo[o], re[j + o]);
            }
        }
    }

    float a = g_A[c], bb = g_B0[c];
    #pragma unroll
    for (int pl = 0; pl < 2; ++pl) {
        ull* aA = pl ? aA1 : aA0;
        ull* aB = pl ? aB1 : aB0;
        float bl[5], bh[5];
        #pragma unroll
        for (int j = 0; j < 5; ++j) unpk2(aB[j], bl[j], bh[j]);
        float o[8];
        #pragma unroll
        for (int i = 0; i < 4; ++i) {
            float alo, ahi; unpk2(aA[i], alo, ahi);
            o[2*i]   = fmaf(a, alo + bh[i],     bb);
            o[2*i+1] = fmaf(a, ahi + bl[i + 1], bb);
        }
        int d = dt + (pp << 1) + pl;
        size_t ob = base + ((size_t)d << 12) + ((ht + hl) << 6) + wbase;
        *(float4*)&g_t0[ob]     = make_float4(o[0], o[1], o[2], o[3]);
        *(float4*)&g_t0[ob + 4] = make_float4(o[4], o[5], o[6], o[7]);
    }
}

// ---------------------------------------------------------------------------
// K3: dilated(3) depthwise 7x7x7 conv. Residue decomposition + zero-pack
// f32x2. 512-thread blocks: each subgrid row's 22 outputs split across two
// w-half threads (overlap pair duplicated, benign). Low regs -> 50% occupancy.
// Weight rows padded to 8 ull for LDS.128.
// ---------------------------------------------------------------------------
#define K3_TILE_FLOATS (17*28*30)
#define K3_SMEM_BYTES (K3_TILE_FLOATS*4 + 392*8)

__global__ __launch_bounds__(512, 2) void k3_conv7(const float* __restrict__ ws) {
    extern __shared__ float smem3[];
    float* sm = smem3;                          // [17][28][30]
    ull*   w2 = (ull*)(smem3 + K3_TILE_FLOATS); // [49 rows][8]

    int bx = blockIdx.x;            // 54 = residue*2 + d-half
    int res = bx >> 1, dhalf = bx & 1;
    int rw = res % 3; int t = res / 3; int rh = t % 3; int rd = t / 3;
    int c = blockIdx.y, n = blockIdx.z;
    int tid = threadIdx.x;
    size_t base = ((size_t)((n << 6) + c) << CH_SHIFT);
    float bsv = g_BS[c];

    for (int i = tid; i < 392; i += 512) {
        int row = i >> 3, lane = i & 7;
        float w = (lane < 7) ? ws[c * 343 + row * 7 + lane] : 0.f;
        w2[i] = pk2(w, w);
    }
    int dofs = rd + 33 * dhalf - 9;
    for (int i = tid; i < 17 * 28 * 28; i += 512) {
        int xs = i % 28; int u = i / 28; int ys = u % 28; int zl = u / 28;
        int d = dofs + 3 * zl;
        int h = rh + 3 * (ys - 3);
        int w = rw + 3 * (xs - 3);
        float v = 0.f;
        if ((unsigned)d < 64u && (unsigned)h < 64u && (unsigned)w < 64u)
            v = g_t0[base + ((size_t)d << 12) + (h << 6) + w];
        sm[(zl * 28 + ys) * 30 + xs] = v;
    }
    __syncthreads();

    int whalf = tid >> 8;           // 0: pairs 0..5, 1: pairs 5..10
    int r = tid & 255;
    if (r < 242) {
        int p = r / 22;             // output plane within half (0..10)
        int hs = r - p * 22;        // output h within subgrid (0..21)
        int i0 = whalf * 5;         // pair base

        ull accA[6], accB[7];
        #pragma unroll
        for (int i = 0; i < 6; ++i) accA[i] = 0ull;
        #pragma unroll
        for (int i = 0; i < 7; ++i) accB[i] = 0ull;

        #pragma unroll 1
        for (int kd = 0; kd < 7; ++kd) {
            const ull* plane = (const ull*)&sm[((p + kd) * 28 + hs) * 30] + i0;
            #pragma unroll 1
            for (int kh = 0; kh < 7; ++kh) {
                const ull* rp = plane + kh * 15;
                ull re[9];
                #pragma unroll
                for (int i = 0; i < 9; ++i) re[i] = rp[i];
                const ull* wp = &w2[(kd * 7 + kh) << 3];
                ulonglong2 wA = *(const ulonglong2*)wp;        // kw0, kw1
                ulonglong2 wB = *(const ulonglong2*)(wp + 2);  // kw2, kw3
                ulonglong2 wC = *(const ulonglong2*)(wp + 4);  // kw4, kw5
                ull w6 = wp[6];
                ull we[4] = {wA.x, wB.x, wC.x, w6};
                ull wo[3] = {wA.y, wB.y, wC.y};
                #pragma unroll
                for (int e = 0; e < 4; ++e)
                    #pragma unroll
                    for (int i = 0; i < 6; ++i) fma2(accA[i], we[e], re[i + e]);
                #pragma unroll
                for (int o = 0; o < 3; ++o)
                    #pragma unroll
                    for (int j = 0; j < 7; ++j) fma2(accB[j], wo[o], re[j + o]);
            }
        }

        int d = rd + 3 * (11 * dhalf + p);
        int h = rh + 3 * hs;
        if (d < 64 && h < 64) {
            size_t ob = base + ((size_t)d << 12) + (h << 6);
            float bl[7], bh[7];
            #pragma unroll
            for (int j = 0; j < 7; ++j) unpk2(accB[j], bl[j], bh[j]);
            #pragma unroll
            for (int i = 0; i < 6; ++i) {
                float alo, ahi; unpk2(accA[i], alo, ahi);
                int gi = i0 + i;
                g_t1[ob + rw + 6 * gi] = alo + bh[i] + bsv;
                int w = rw + 6 * gi + 3;
                if (w < 64) g_t1[ob + w] = ahi + bl[i + 1] + bsv;
            }
        }
    }
}

// ---------------------------------------------------------------------------
// K4: pointwise 64x64 conv + bias + gated residual. f32x2, direct ull smem
// loads, weights via __ldg of pre-packed pairs.
// ---------------------------------------------------------------------------
#define K4_SMEM_BYTES (64*256*4)

__global__ __launch_bounds__(256) void k4_point(const float* __restrict__ x,
                                                float* __restrict__ out) {
    extern __shared__ float s4[];
    float* vt = s4;             // [64 ci][256 px]
    int n = blockIdx.y;
    int pb = blockIdx.x << 8;
    int tid = threadIdx.x;
    size_t nb = ((size_t)n << 24);

    #pragma unroll 4
    for (int ci = 0; ci < 64; ++ci)
        vt[(ci << 8) + tid] = g_t1[nb + ((size_t)ci << CH_SHIFT) + pb + tid];
    __syncthreads();

    int pgi = tid & 31;
    int cgi = tid >> 5;
    int px0 = pgi << 3;
    int co0 = cgi << 3;

    ull acc[8][4];
    #pragma unroll
    for (int k = 0; k < 8; ++k)
        #pragma unroll
        for (int j = 0; j < 4; ++j) acc[k][j] = 0ull;

    #pragma unroll 2
    for (int ci = 0; ci < 64; ++ci) {
        const ull* vp = (const ull*)(vt + (ci << 8) + px0);
        ull p0 = vp[0], p1 = vp[1], p2 = vp[2], p3 = vp[3];
        const ull* wrow = &g_w1p[(co0 << 6) + ci];
        #pragma unroll
        for (int k = 0; k < 8; ++k) {
            ull w = __ldg(&wrow[k << 6]);
            fma2(acc[k][0], w, p0);
            fma2(acc[k][1], w, p1);
            fma2(acc[k][2], w, p2);
            fma2(acc[k][3], w, p3);
        }
    }

    #pragma unroll 1
    for (int k = 0; k < 8; ++k) {
        int co = co0 + k;
        float bv = g_B1[co];
        size_t gb = nb + ((size_t)co << CH_SHIFT) + pb + px0;
        float4 xa = *(const float4*)&x[gb];
        float4 xb = *(const float4*)&x[gb + 4];
        float o[8];
        #pragma unroll
        for (int j = 0; j < 4; ++j) {
            float lo, hi; unpk2(acc[k][j], lo, hi);
            o[2*j] = lo + bv; o[2*j+1] = hi + bv;
        }
        float4 ra = make_float4(xa.x*o[0], xa.y*o[1], xa.z*o[2], xa.w*o[3]);
        float4 rb = make_float4(xb.x*o[4], xb.y*o[5], xb.z*o[6], xb.w*o[7]);
        *(float4*)&out[gb]     = ra;
        *(float4*)&out[gb + 4] = rb;
    }
}

// ---------------------------------------------------------------------------
extern "C" void kernel_launch(void* const* d_in, const int* in_sizes, int n_in,
                              void* d_out, int out_size) {
    const float *x = 0, *w0 = 0, *ws = 0, *w1 = 0;
    const float* small[5] = {0, 0, 0, 0, 0};
    int ns = 0;
    for (int i = 0; i < n_in; ++i) {
        const float* p = (const float*)d_in[i];
        switch (in_sizes[i]) {
            case TOTAL:  x  = p; break;
            case 8000:   w0 = p; break;
            case 21952:  ws = p; break;
            case 4096:   w1 = p; break;
            case 64:     if (ns < 5) small[ns++] = p; break;
            default: break;
        }
    }
    if (!x || !w0 || !ws || !w1 || ns != 5) {
        x = (const float*)d_in[0];
        small[0] = (const float*)d_in[1];
        small[1] = (const float*)d_in[2];
        w0 = (const float*)d_in[3];
        small[2] = (const float*)d_in[4];
        ws = (const float*)d_in[5];
        small[3] = (const float*)d_in[6];
        w1 = (const float*)d_in[7];
        small[4] = (const float*)d_in[8];
    }
    float* out = (float*)d_out;

    cudaFuncSetAttribute(k3_conv7, cudaFuncAttributeMaxDynamicSharedMemorySize, K3_SMEM_BYTES);
    cudaFuncSetAttribute(k4_point, cudaFuncAttributeMaxDynamicSharedMemorySize, K4_SMEM_BYTES);

    k1_stats<<<dim3(64, 64), 256>>>(x);
    k1_final<<<1, 64>>>(small[0], small[1], small[2], small[3], small[4], w0);
    k4_packw<<<16, 256>>>(w1);
    k2_conv5<<<dim3(64, 64, 2), 256>>>(x, w0);
    k3_conv7<<<dim3(54, 64, 2), 512, K3_SMEM_BYTES>>>(ws);
    k4_point<<<dim3(1024, 2), 256, K4_SMEM_BYTES>>>(x, out);
}

// round 13
// speedup vs baseline: 1.5796x; 1.5796x over previous
#include <cuda_runtime.h>
#include <cstdint>

typedef unsigned long long ull;

#define NB 2
#define CH 64
#define DS 64
#define VOL (DS*DS*DS)
#define CH_SHIFT 18
#define TOTAL (NB*CH*VOL)

__device__ float  g_t0[TOTAL];
__device__ float  g_t1[TOTAL];
__device__ float2 g_part[64*64];
__device__ float  g_A[CH], g_B0[CH], g_PAD[CH], g_BS[CH], g_B1[CH];
__device__ ull    g_w1p[4096];

// ---------------------------------------------------------------------------
__device__ __forceinline__ ull pk2(float a, float b) {
    ull r;
    asm("mov.b64 %0, {%1, %2};" : "=l"(r) : "f"(a), "f"(b));
    return r;
}
__device__ __forceinline__ void unpk2(ull v, float& lo, float& hi) {
    asm("mov.b64 {%0, %1}, %2;" : "=f"(lo), "=f"(hi) : "l"(v));
}
__device__ __forceinline__ void fma2(ull& d, ull a, ull b) {
    asm("fma.rn.f32x2 %0, %1, %2, %0;" : "+l"(d) : "l"(a), "l"(b));
}

// ---------------------------------------------------------------------------
// K1: per-channel partial sums.
// ---------------------------------------------------------------------------
__global__ __launch_bounds__(256) void k1_stats(const float* __restrict__ x) {
    int b = blockIdx.x, c = blockIdx.y;
    int n = b >> 5, chunk = b & 31;
    size_t base = ((size_t)((n << 6) + c) << CH_SHIFT) + ((size_t)chunk << 13);
    const float4* p = (const float4*)(x + base);
    float s = 0.f, q = 0.f;
    #pragma unroll
    for (int it = 0; it < 8; ++it) {
        float4 v = p[(it << 8) + threadIdx.x];
        s += v.x + v.y + v.z + v.w;
        q += v.x*v.x + v.y*v.y + v.z*v.z + v.w*v.w;
    }
    #pragma unroll
    for (int o = 16; o; o >>= 1) {
        s += __shfl_down_sync(0xffffffffu, s, o);
        q += __shfl_down_sync(0xffffffffu, q, o);
    }
    __shared__ float ss[8], qq[8];
    int w = threadIdx.x >> 5, l = threadIdx.x & 31;
    if (l == 0) { ss[w] = s; qq[w] = q; }
    __syncthreads();
    if (threadIdx.x == 0) {
        float S = 0.f, Q = 0.f;
        #pragma unroll
        for (int i = 0; i < 8; ++i) { S += ss[i]; Q += qq[i]; }
        g_part[(c << 6) + b] = make_float2(S, Q);
    }
}

__global__ void k1_final(const float* __restrict__ v0, const float* __restrict__ v1,
                         const float* __restrict__ v2, const float* __restrict__ v3,
                         const float* __restrict__ v4, const float* __restrict__ w0) {
    int c = threadIdx.x;
    if (c >= CH) return;
    const float* vs[5] = {v0, v1, v2, v3, v4};
    float sums[5];
    for (int i = 0; i < 5; ++i) {
        float s = 0.f;
        for (int j = 0; j < CH; ++j) s += vs[i][j];
        sums[i] = s;
    }
    int gi = -1, ok = 1;
    for (int i = 0; i < 5; ++i) {
        if (fabsf(sums[i] - 64.f) < 1.f) { if (gi < 0) gi = i; else ok = 0; }
        else if (fabsf(sums[i]) > 1.f) ok = 0;
    }
    if (!ok || gi < 0) gi = 0;
    const float* gamma = vs[gi];
    const float* rest[4]; int r = 0;
    for (int i = 0; i < 5; ++i) if (i != gi) rest[r++] = vs[i];
    const float* beta = rest[0];
    const float* b0   = rest[1];
    const float* bs   = rest[2];
    const float* b1   = rest[3];

    float S = 0.f, Q = 0.f;
    for (int b = 0; b < 64; ++b) { float2 p = g_part[(c << 6) + b]; S += p.x; Q += p.y; }
    const float inv = 1.0f / (float)(NB * VOL);
    float mean = S * inv;
    float var = fmaf(Q, inv, -mean * mean);
    if (var < 0.f) var = 0.f;
    float a = gamma[c] * rsqrtf(var + 1e-5f);
    float e = beta[c] - mean * a;
    float s0 = 0.f;
    for (int t = 0; t < 125; ++t) s0 += w0[c * 125 + t];
    g_A[c]   = a;
    g_B0[c]  = fmaf(e, s0, b0[c]);
    g_PAD[c] = (a != 0.0f) ? (-e / a) : 0.0f;
    g_BS[c]  = bs[c];
    g_B1[c]  = b1[c];
}

__global__ void k4_packw(const float* __restrict__ w1) {
    int i = blockIdx.x * 256 + threadIdx.x;
    if (i < 4096) { float w = w1[i]; g_w1p[i] = pk2(w, w); }
}

// ---------------------------------------------------------------------------
// K2: depthwise 5x5x5 conv (pad 2), BN folded. Zero-pack f32x2, direct ull
// smem loads, kh loop NOT unrolled (regs <= 64), 4 blocks/SM.  (R11 version)
// ---------------------------------------------------------------------------
__global__ __launch_bounds__(256, 4) void k2_conv5(const float* __restrict__ x,
                                                   const float* __restrict__ w0) {
    __shared__ float sm[12 * 12 * 68];
    __shared__ ull w2s[125];
    int c = blockIdx.y, n = blockIdx.z;
    int dt = (blockIdx.x >> 3) << 3;
    int ht = (blockIdx.x & 7) << 3;
    int tid = threadIdx.x;
    size_t base = ((size_t)((n << 6) + c) << CH_SHIFT);

    float pad = g_PAD[c];
    if (tid < 125) { float w = w0[c * 125 + tid]; w2s[tid] = pk2(w, w); }
    for (int i = tid; i < 12 * 12 * 68; i += 256) {
        int wx = i % 68; int t = i / 68; int hy = t % 12; int dz = t / 12;
        int d = dt + dz - 2, h = ht + hy - 2, w = wx - 2;
        float v = pad;
        if ((unsigned)d < 64u && (unsigned)h < 64u && (unsigned)w < 64u)
            v = x[base + ((size_t)d << 12) + (h << 6) + w];
        sm[i] = v;
    }
    __syncthreads();

    int wg = tid & 7;
    int hl = (tid >> 3) & 7;
    int pp = tid >> 6;
    int wbase = wg << 3;

    ull aA0[4], aB0[5], aA1[4], aB1[5];
    #pragma unroll
    for (int i = 0; i < 4; ++i) { aA0[i] = 0ull; aA1[i] = 0ull; }
    #pragma unroll
    for (int i = 0; i < 5; ++i) { aB0[i] = 0ull; aB1[i] = 0ull; }

    #pragma unroll 1
    for (int kdp = 0; kdp < 6; ++kdp) {
        int z = (pp << 1) + kdp;
        const ull* zrow = (const ull*)&sm[(z * 12 + hl) * 68 + wbase];
        #pragma unroll 1
        for (int kh = 0; kh < 5; ++kh) {
            const ull* rp = zrow + kh * 34;
            ull re[6];
            #pragma unroll
            for (int i = 0; i < 6; ++i) re[i] = rp[i];
            if (kdp < 5) {
                const ull* wp = &w2s[(kdp * 5 + kh) * 5];
                #pragma unroll
                for (int e = 0; e < 3; ++e) {
                    ull w = wp[2 * e];
                    #pragma unroll
                    for (int i = 0; i < 4; ++i) fma2(aA0[i], w, re[i + e]);
                }
                #pragma unroll
                for (int o = 0; o < 2; ++o) {
                    ull w = wp[2 * o + 1];
                    #pragma unroll
                    for (int j = 0; j < 5; ++j) fma2(aB0[j], w, re[j + o]);
                }
            }
            if (kdp >= 1) {
                const ull* wp = &w2s[((kdp - 1) * 5 + kh) * 5];
                #pragma unroll
                for (int e = 0; e < 3; ++e) {
                    ull w = wp[2 * e];
                    #pragma unroll
                    for (int i = 0; i < 4; ++i) fma2(aA1[i], w, re[i + e]);
                }
                #pragma unroll
                for (int o = 0; o < 2; ++o) {
                    ull w = wp[2 * o + 1];
                    #pragma unroll
                    for (int j = 0; j < 5; ++j) fma2(aB1[j], w, re[j + o]);
                }
            }
        }
    }

    float a = g_A[c], bb = g_B0[c];
    #pragma unroll
    for (int pl = 0; pl < 2; ++pl) {
        ull* aA = pl ? aA1 : aA0;
        ull* aB = pl ? aB1 : aB0;
        float bl[5], bh[5];
        #pragma unroll
        for (int j = 0; j < 5; ++j) unpk2(aB[j], bl[j], bh[j]);
        float o[8];
        #pragma unroll
        for (int i = 0; i < 4; ++i) {
            float alo, ahi; unpk2(aA[i], alo, ahi);
            o[2*i]   = fmaf(a, alo + bh[i],     bb);
            o[2*i+1] = fmaf(a, ahi + bl[i + 1], bb);
        }
        int d = dt + (pp << 1) + pl;
        size_t ob = base + ((size_t)d << 12) + ((ht + hl) << 6) + wbase;
        *(float4*)&g_t0[ob]     = make_float4(o[0], o[1], o[2], o[3]);
        *(float4*)&g_t0[ob + 4] = make_float4(o[4], o[5], o[6], o[7]);
    }
}

// ---------------------------------------------------------------------------
// K3: dilated(3) depthwise 7x7x7 conv. Residue decomposition + zero-pack
// f32x2. 256 threads; each thread processes its row in TWO sequential
// w-halves (pairs 0..5 then 5..10) -> 13 ull accs live at a time -> fits
// 85-reg cap at 3 blocks/SM (37.5% occ). Shared pair recomputed (benign).
// ---------------------------------------------------------------------------
#define K3_TILE_FLOATS (17*28*30)
#define K3_SMEM_BYTES (K3_TILE_FLOATS*4 + 343*8)

__global__ __launch_bounds__(256, 3) void k3_conv7(const float* __restrict__ ws) {
    extern __shared__ float smem3[];
    float* sm = smem3;                          // [17][28][30]
    ull*   w2 = (ull*)(smem3 + K3_TILE_FLOATS); // [343]

    int bx = blockIdx.x;            // 54 = residue*2 + d-half
    int res = bx >> 1, dhalf = bx & 1;
    int rw = res % 3; int t = res / 3; int rh = t % 3; int rd = t / 3;
    int c = blockIdx.y, n = blockIdx.z;
    int tid = threadIdx.x;
    size_t base = ((size_t)((n << 6) + c) << CH_SHIFT);
    float bsv = g_BS[c];

    for (int i = tid; i < 343; i += 256) { float w = ws[c * 343 + i]; w2[i] = pk2(w, w); }
    int dofs = rd + 33 * dhalf - 9;
    for (int i = tid; i < 17 * 28 * 28; i += 256) {
        int xs = i % 28; int u = i / 28; int ys = u % 28; int zl = u / 28;
        int d = dofs + 3 * zl;
        int h = rh + 3 * (ys - 3);
        int w = rw + 3 * (xs - 3);
        float v = 0.f;
        if ((unsigned)d < 64u && (unsigned)h < 64u && (unsigned)w < 64u)
            v = g_t0[base + ((size_t)d << 12) + (h << 6) + w];
        sm[(zl * 28 + ys) * 30 + xs] = v;
    }
    __syncthreads();

    if (tid < 242) {
        int p = tid / 22;           // output plane within d-half (0..10)
        int hs = tid - p * 22;      // output h within subgrid (0..21)
        int d = rd + 3 * (11 * dhalf + p);
        int h = rh + 3 * hs;
        bool valid = (d < 64) && (h < 64);
        size_t ob = base + ((size_t)d << 12) + (h << 6);

        #pragma unroll 1
        for (int whalf = 0; whalf < 2; ++whalf) {
            int i0 = whalf * 5;     // pair base: 0..5 or 5..10

            ull accA[6], accB[7];
            #pragma unroll
            for (int i = 0; i < 6; ++i) accA[i] = 0ull;
            #pragma unroll
            for (int i = 0; i < 7; ++i) accB[i] = 0ull;

            #pragma unroll 1
            for (int kd = 0; kd < 7; ++kd) {
                const ull* plane = (const ull*)&sm[((p + kd) * 28 + hs) * 30] + i0;
                #pragma unroll 1
                for (int kh = 0; kh < 7; ++kh) {
                    const ull* rp = plane + kh * 15;
                    ull re[9];
                    #pragma unroll
                    for (int i = 0; i < 9; ++i) re[i] = rp[i];
                    const ull* wp = &w2[(kd * 7 + kh) * 7];
                    #pragma unroll
                    for (int e = 0; e < 4; ++e) {        // kw = 2e
                        ull w = wp[2 * e];
                        #pragma unroll
                        for (int i = 0; i < 6; ++i) fma2(accA[i], w, re[i + e]);
                    }
                    #pragma unroll
                    for (int o = 0; o < 3; ++o) {        // kw = 2o+1
                        ull w = wp[2 * o + 1];
                        #pragma unroll
                        for (int j = 0; j < 7; ++j) fma2(accB[j], w, re[j + o]);
                    }
                }
            }

            if (valid) {
                float bl[7], bh[7];
                #pragma unroll
                for (int j = 0; j < 7; ++j) unpk2(accB[j], bl[j], bh[j]);
                #pragma unroll
                for (int i = 0; i < 6; ++i) {
                    float alo, ahi; unpk2(accA[i], alo, ahi);
                    int gi = i0 + i;
                    g_t1[ob + rw + 6 * gi] = alo + bh[i] + bsv;
                    int w = rw + 6 * gi + 3;
                    if (w < 64) g_t1[ob + w] = ahi + bl[i + 1] + bsv;
                }
            }
        }
    }
}

// ---------------------------------------------------------------------------
// K4: pointwise 64x64 conv + bias + gated residual. (R11 version)
// ---------------------------------------------------------------------------
#define K4_SMEM_BYTES (64*256*4)

__global__ __launch_bounds__(256) void k4_point(const float* __restrict__ x,
                                                float* __restrict__ out) {
    extern __shared__ float s4[];
    float* vt = s4;             // [64 ci][256 px]
    int n = blockIdx.y;
    int pb = blockIdx.x << 8;
    int tid = threadIdx.x;
    size_t nb = ((size_t)n << 24);

    #pragma unroll 4
    for (int ci = 0; ci < 64; ++ci)
        vt[(ci << 8) + tid] = g_t1[nb + ((size_t)ci << CH_SHIFT) + pb + tid];
    __syncthreads();

    int pgi = tid & 31;
    int cgi = tid >> 5;
    int px0 = pgi << 3;
    int co0 = cgi << 3;

    ull acc[8][4];
    #pragma unroll
    for (int k = 0; k < 8; ++k)
        #pragma unroll
        for (int j = 0; j < 4; ++j) acc[k][j] = 0ull;

    #pragma unroll 2
    for (int ci = 0; ci < 64; ++ci) {
        const ull* vp = (const ull*)(vt + (ci << 8) + px0);
        ull p0 = vp[0], p1 = vp[1], p2 = vp[2], p3 = vp[3];
        const ull* wrow = &g_w1p[(co0 << 6) + ci];
        #pragma unroll
        for (int k = 0; k < 8; ++k) {
            ull w = __ldg(&wrow[k << 6]);
            fma2(acc[k][0], w, p0);
            fma2(acc[k][1], w, p1);
            fma2(acc[k][2], w, p2);
            fma2(acc[k][3], w, p3);
        }
    }

    #pragma unroll 1
    for (int k = 0; k < 8; ++k) {
        int co = co0 + k;
        float bv = g_B1[co];
        size_t gb = nb + ((size_t)co << CH_SHIFT) + pb + px0;
        float4 xa = *(const float4*)&x[gb];
        float4 xb = *(const float4*)&x[gb + 4];
        float o[8];
        #pragma unroll
        for (int j = 0; j < 4; ++j) {
            float lo, hi; unpk2(acc[k][j], lo, hi);
            o[2*j] = lo + bv; o[2*j+1] = hi + bv;
        }
        float4 ra = make_float4(xa.x*o[0], xa.y*o[1], xa.z*o[2], xa.w*o[3]);
        float4 rb = make_float4(xb.x*o[4], xb.y*o[5], xb.z*o[6], xb.w*o[7]);
        *(float4*)&out[gb]     = ra;
        *(float4*)&out[gb + 4] = rb;
    }
}

// ---------------------------------------------------------------------------
extern "C" void kernel_launch(void* const* d_in, const int* in_sizes, int n_in,
                              void* d_out, int out_size) {
    const float *x = 0, *w0 = 0, *ws = 0, *w1 = 0;
    const float* small[5] = {0, 0, 0, 0, 0};
    int ns = 0;
    for (int i = 0; i < n_in; ++i) {
        const float* p = (const float*)d_in[i];
        switch (in_sizes[i]) {
            case TOTAL:  x  = p; break;
            case 8000:   w0 = p; break;
            case 21952:  ws = p; break;
            case 4096:   w1 = p; break;
            case 64:     if (ns < 5) small[ns++] = p; break;
            default: break;
        }
    }
    if (!x || !w0 || !ws || !w1 || ns != 5) {
        x = (const float*)d_in[0];
        small[0] = (const float*)d_in[1];
        small[1] = (const float*)d_in[2];
        w0 = (const float*)d_in[3];
        small[2] = (const float*)d_in[4];
        ws = (const float*)d_in[5];
        small[3] = (const float*)d_in[6];
        w1 = (const float*)d_in[7];
        small[4] = (const float*)d_in[8];
    }
    float* out = (float*)d_out;

    cudaFuncSetAttribute(k3_conv7, cudaFuncAttributeMaxDynamicSharedMemorySize, K3_SMEM_BYTES);
    cudaFuncSetAttribute(k4_point, cudaFuncAttributeMaxDynamicSharedMemorySize, K4_SMEM_BYTES);

    k1_stats<<<dim3(64, 64), 256>>>(x);
    k1_final<<<1, 64>>>(small[0], small[1], small[2], small[3], small[4], w0);
    k4_packw<<<16, 256>>>(w1);
    k2_conv5<<<dim3(64, 64, 2), 256>>>(x, w0);
    k3_conv7<<<dim3(54, 64, 2), 256, K3_SMEM_BYTES>>>(ws);
    k4_point<<<dim3(1024, 2), 256, K4_SMEM_BYTES>>>(x, out);
}

// round 14
// speedup vs baseline: 1.7485x; 1.1069x over previous
#include <cuda_runtime.h>
#include <cstdint>

typedef unsigned long long ull;

#define NB 2
#define CH 64
#define DS 64
#define VOL (DS*DS*DS)
#define CH_SHIFT 18
#define TOTAL (NB*CH*VOL)

__device__ float  g_t0[TOTAL];
__device__ float  g_t1[TOTAL];
__device__ float2 g_part[64*64];
__device__ float  g_A[CH], g_B0[CH], g_PAD[CH], g_BS[CH], g_B1[CH];
__device__ ull    g_w1p[4096];

// ---------------------------------------------------------------------------
__device__ __forceinline__ ull pk2(float a, float b) {
    ull r;
    asm("mov.b64 %0, {%1, %2};" : "=l"(r) : "f"(a), "f"(b));
    return r;
}
__device__ __forceinline__ void unpk2(ull v, float& lo, float& hi) {
    asm("mov.b64 {%0, %1}, %2;" : "=f"(lo), "=f"(hi) : "l"(v));
}
__device__ __forceinline__ void fma2(ull& d, ull a, ull b) {
    asm("fma.rn.f32x2 %0, %1, %2, %0;" : "+l"(d) : "l"(a), "l"(b));
}

// ---------------------------------------------------------------------------
// K1: per-channel partial sums.
// ---------------------------------------------------------------------------
__global__ __launch_bounds__(256) void k1_stats(const float* __restrict__ x) {
    int b = blockIdx.x, c = blockIdx.y;
    int n = b >> 5, chunk = b & 31;
    size_t base = ((size_t)((n << 6) + c) << CH_SHIFT) + ((size_t)chunk << 13);
    const float4* p = (const float4*)(x + base);
    float s = 0.f, q = 0.f;
    #pragma unroll
    for (int it = 0; it < 8; ++it) {
        float4 v = p[(it << 8) + threadIdx.x];
        s += v.x + v.y + v.z + v.w;
        q += v.x*v.x + v.y*v.y + v.z*v.z + v.w*v.w;
    }
    #pragma unroll
    for (int o = 16; o; o >>= 1) {
        s += __shfl_down_sync(0xffffffffu, s, o);
        q += __shfl_down_sync(0xffffffffu, q, o);
    }
    __shared__ float ss[8], qq[8];
    int w = threadIdx.x >> 5, l = threadIdx.x & 31;
    if (l == 0) { ss[w] = s; qq[w] = q; }
    __syncthreads();
    if (threadIdx.x == 0) {
        float S = 0.f, Q = 0.f;
        #pragma unroll
        for (int i = 0; i < 8; ++i) { S += ss[i]; Q += qq[i]; }
        g_part[(c << 6) + b] = make_float2(S, Q);
    }
}

__global__ void k1_final(const float* __restrict__ v0, const float* __restrict__ v1,
                         const float* __restrict__ v2, const float* __restrict__ v3,
                         const float* __restrict__ v4, const float* __restrict__ w0) {
    int c = threadIdx.x;
    if (c >= CH) return;
    const float* vs[5] = {v0, v1, v2, v3, v4};
    float sums[5];
    for (int i = 0; i < 5; ++i) {
        float s = 0.f;
        for (int j = 0; j < CH; ++j) s += vs[i][j];
        sums[i] = s;
    }
    int gi = -1, ok = 1;
    for (int i = 0; i < 5; ++i) {
        if (fabsf(sums[i] - 64.f) < 1.f) { if (gi < 0) gi = i; else ok = 0; }
        else if (fabsf(sums[i]) > 1.f) ok = 0;
    }
    if (!ok || gi < 0) gi = 0;
    const float* gamma = vs[gi];
    const float* rest[4]; int r = 0;
    for (int i = 0; i < 5; ++i) if (i != gi) rest[r++] = vs[i];
    const float* beta = rest[0];
    const float* b0   = rest[1];
    const float* bs   = rest[2];
    const float* b1   = rest[3];

    float S = 0.f, Q = 0.f;
    for (int b = 0; b < 64; ++b) { float2 p = g_part[(c << 6) + b]; S += p.x; Q += p.y; }
    const float inv = 1.0f / (float)(NB * VOL);
    float mean = S * inv;
    float var = fmaf(Q, inv, -mean * mean);
    if (var < 0.f) var = 0.f;
    float a = gamma[c] * rsqrtf(var + 1e-5f);
    float e = beta[c] - mean * a;
    float s0 = 0.f;
    for (int t = 0; t < 125; ++t) s0 += w0[c * 125 + t];
    g_A[c]   = a;
    g_B0[c]  = fmaf(e, s0, b0[c]);
    g_PAD[c] = (a != 0.0f) ? (-e / a) : 0.0f;
    g_BS[c]  = bs[c];
    g_B1[c]  = b1[c];
}

__global__ void k4_packw(const float* __restrict__ w1) {
    int i = blockIdx.x * 256 + threadIdx.x;
    if (i < 4096) { float w = w1[i]; g_w1p[i] = pk2(w, w); }
}

// ---------------------------------------------------------------------------
// K2: depthwise 5x5x5 conv (pad 2), BN folded. (R11 version: zero-pack f32x2,
// direct ull smem loads, kh loop not unrolled, 4 blocks/SM.)
// ---------------------------------------------------------------------------
__global__ __launch_bounds__(256, 4) void k2_conv5(const float* __restrict__ x,
                                                   const float* __restrict__ w0) {
    __shared__ float sm[12 * 12 * 68];
    __shared__ ull w2s[125];
    int c = blockIdx.y, n = blockIdx.z;
    int dt = (blockIdx.x >> 3) << 3;
    int ht = (blockIdx.x & 7) << 3;
    int tid = threadIdx.x;
    size_t base = ((size_t)((n << 6) + c) << CH_SHIFT);

    float pad = g_PAD[c];
    if (tid < 125) { float w = w0[c * 125 + tid]; w2s[tid] = pk2(w, w); }
    for (int i = tid; i < 12 * 12 * 68; i += 256) {
        int wx = i % 68; int t = i / 68; int hy = t % 12; int dz = t / 12;
        int d = dt + dz - 2, h = ht + hy - 2, w = wx - 2;
        float v = pad;
        if ((unsigned)d < 64u && (unsigned)h < 64u && (unsigned)w < 64u)
            v = x[base + ((size_t)d << 12) + (h << 6) + w];
        sm[i] = v;
    }
    __syncthreads();

    int wg = tid & 7;
    int hl = (tid >> 3) & 7;
    int pp = tid >> 6;
    int wbase = wg << 3;

    ull aA0[4], aB0[5], aA1[4], aB1[5];
    #pragma unroll
    for (int i = 0; i < 4; ++i) { aA0[i] = 0ull; aA1[i] = 0ull; }
    #pragma unroll
    for (int i = 0; i < 5; ++i) { aB0[i] = 0ull; aB1[i] = 0ull; }

    #pragma unroll 1
    for (int kdp = 0; kdp < 6; ++kdp) {
        int z = (pp << 1) + kdp;
        const ull* zrow = (const ull*)&sm[(z * 12 + hl) * 68 + wbase];
        #pragma unroll 1
        for (int kh = 0; kh < 5; ++kh) {
            const ull* rp = zrow + kh * 34;
            ull re[6];
            #pragma unroll
            for (int i = 0; i < 6; ++i) re[i] = rp[i];
            if (kdp < 5) {
                const ull* wp = &w2s[(kdp * 5 + kh) * 5];
                #pragma unroll
                for (int e = 0; e < 3; ++e) {
                    ull w = wp[2 * e];
                    #pragma unroll
                    for (int i = 0; i < 4; ++i) fma2(aA0[i], w, re[i + e]);
                }
                #pragma unroll
                for (int o = 0; o < 2; ++o) {
                    ull w = wp[2 * o + 1];
                    #pragma unroll
                    for (int j = 0; j < 5; ++j) fma2(aB0[j], w, re[j + o]);
                }
            }
            if (kdp >= 1) {
                const ull* wp = &w2s[((kdp - 1) * 5 + kh) * 5];
                #pragma unroll
                for (int e = 0; e < 3; ++e) {
                    ull w = wp[2 * e];
                    #pragma unroll
                    for (int i = 0; i < 4; ++i) fma2(aA1[i], w, re[i + e]);
                }
                #pragma unroll
                for (int o = 0; o < 2; ++o) {
                    ull w = wp[2 * o + 1];
                    #pragma unroll
                    for (int j = 0; j < 5; ++j) fma2(aB1[j], w, re[j + o]);
                }
            }
        }
    }

    float a = g_A[c], bb = g_B0[c];
    #pragma unroll
    for (int pl = 0; pl < 2; ++pl) {
        ull* aA = pl ? aA1 : aA0;
        ull* aB = pl ? aB1 : aB0;
        float bl[5], bh[5];
        #pragma unroll
        for (int j = 0; j < 5; ++j) unpk2(aB[j], bl[j], bh[j]);
        float o[8];
        #pragma unroll
        for (int i = 0; i < 4; ++i) {
            float alo, ahi; unpk2(aA[i], alo, ahi);
            o[2*i]   = fmaf(a, alo + bh[i],     bb);
            o[2*i+1] = fmaf(a, ahi + bl[i + 1], bb);
        }
        int d = dt + (pp << 1) + pl;
        size_t ob = base + ((size_t)d << 12) + ((ht + hl) << 6) + wbase;
        *(float4*)&g_t0[ob]     = make_float4(o[0], o[1], o[2], o[3]);
        *(float4*)&g_t0[ob + 4] = make_float4(o[4], o[5], o[6], o[7]);
    }
}

// ---------------------------------------------------------------------------
// K3: dilated(3) depthwise 7x7x7 conv. Residue decomposition + zero-pack
// f32x2, STREAMING row application: each loaded ull immediately feeds its
// (statically bounded) acc window -> ~3 re live instead of 14 -> regs fit
// 3 blocks/SM (37.5% occ) with identical LDS and FMA2 counts.
// Full 22-wide row per thread; half-d tile (11 out planes, 17 in planes).
// ---------------------------------------------------------------------------
#define K3_TILE_FLOATS (17*28*30)
#define K3_SMEM_BYTES (K3_TILE_FLOATS*4 + 343*8)

__global__ __launch_bounds__(256, 3) void k3_conv7(const float* __restrict__ ws) {
    extern __shared__ float smem3[];
    float* sm = smem3;                          // [17][28][30]
    ull*   w2 = (ull*)(smem3 + K3_TILE_FLOATS); // [343]

    int bx = blockIdx.x;            // 54 = residue*2 + d-half
    int res = bx >> 1, dhalf = bx & 1;
    int rw = res % 3; int t = res / 3; int rh = t % 3; int rd = t / 3;
    int c = blockIdx.y, n = blockIdx.z;
    int tid = threadIdx.x;
    size_t base = ((size_t)((n << 6) + c) << CH_SHIFT);
    float bsv = g_BS[c];

    for (int i = tid; i < 343; i += 256) { float w = ws[c * 343 + i]; w2[i] = pk2(w, w); }
    int dofs = rd + 33 * dhalf - 9;
    for (int i = tid; i < 17 * 28 * 28; i += 256) {
        int xs = i % 28; int u = i / 28; int ys = u % 28; int zl = u / 28;
        int d = dofs + 3 * zl;
        int h = rh + 3 * (ys - 3);
        int w = rw + 3 * (xs - 3);
        float v = 0.f;
        if ((unsigned)d < 64u && (unsigned)h < 64u && (unsigned)w < 64u)
            v = g_t0[base + ((size_t)d << 12) + (h << 6) + w];
        sm[(zl * 28 + ys) * 30 + xs] = v;
    }
    __syncthreads();

    if (tid < 242) {
        int p = tid / 22;           // output plane within d-half (0..10)
        int hs = tid - p * 22;      // output h within subgrid (0..21)

        ull accA[11], accB[12];
        #pragma unroll
        for (int i = 0; i < 11; ++i) accA[i] = 0ull;
        #pragma unroll
        for (int i = 0; i < 12; ++i) accB[i] = 0ull;

        #pragma unroll 1
        for (int kd = 0; kd < 7; ++kd) {
            const ull* plane = (const ull*)&sm[((p + kd) * 28 + hs) * 30];
            #pragma unroll 1
            for (int kh = 0; kh < 7; ++kh) {
                const ull* rp = plane + kh * 15;
                const ull* wp = &w2[(kd * 7 + kh) * 7];
                ull we[4], wo[3];
                #pragma unroll
                for (int e = 0; e < 4; ++e) we[e] = wp[2 * e];
                #pragma unroll
                for (int o = 0; o < 3; ++o) wo[o] = wp[2 * o + 1];
                // streaming application: data index i feeds accA[i-3..i],
                // accB[i-2..i] (clamped) -> only a few re live at once.
                #pragma unroll
                for (int i = 0; i < 14; ++i) {
                    ull r = rp[i];
                    #pragma unroll
                    for (int e = 0; e < 4; ++e) {
                        int k = i - e;
                        if (k >= 0 && k <= 10) fma2(accA[k], we[e], r);
                    }
                    #pragma unroll
                    for (int o = 0; o < 3; ++o) {
                        int k = i - o;
                        if (k >= 0 && k <= 11) fma2(accB[k], wo[o], r);
                    }
                }
            }
        }

        int d = rd + 3 * (11 * dhalf + p);
        int h = rh + 3 * hs;
        if (d < 64 && h < 64) {
            size_t ob = base + ((size_t)d << 12) + (h << 6);
            float bl[12], bh[12];
            #pragma unroll
            for (int j = 0; j < 12; ++j) unpk2(accB[j], bl[j], bh[j]);
            #pragma unroll
            for (int i = 0; i < 11; ++i) {
                float alo, ahi; unpk2(accA[i], alo, ahi);
                g_t1[ob + rw + 6 * i] = alo + bh[i] + bsv;
                int w = rw + 6 * i + 3;
                if (w < 64) g_t1[ob + w] = ahi + bl[i + 1] + bsv;
            }
        }
    }
}

// ---------------------------------------------------------------------------
// K4: pointwise 64x64 conv + bias + gated residual. (R11 version)
// ---------------------------------------------------------------------------
#define K4_SMEM_BYTES (64*256*4)

__global__ __launch_bounds__(256) void k4_point(const float* __restrict__ x,
                                                float* __restrict__ out) {
    extern __shared__ float s4[];
    float* vt = s4;             // [64 ci][256 px]
    int n = blockIdx.y;
    int pb = blockIdx.x << 8;
    int tid = threadIdx.x;
    size_t nb = ((size_t)n << 24);

    #pragma unroll 4
    for (int ci = 0; ci < 64; ++ci)
        vt[(ci << 8) + tid] = g_t1[nb + ((size_t)ci << CH_SHIFT) + pb + tid];
    __syncthreads();

    int pgi = tid & 31;
    int cgi = tid >> 5;
    int px0 = pgi << 3;
    int co0 = cgi << 3;

    ull acc[8][4];
    #pragma unroll
    for (int k = 0; k < 8; ++k)
        #pragma unroll
        for (int j = 0; j < 4; ++j) acc[k][j] = 0ull;

    #pragma unroll 2
    for (int ci = 0; ci < 64; ++ci) {
        const ull* vp = (const ull*)(vt + (ci << 8) + px0);
        ull p0 = vp[0], p1 = vp[1], p2 = vp[2], p3 = vp[3];
        const ull* wrow = &g_w1p[(co0 << 6) + ci];
        #pragma unroll
        for (int k = 0; k < 8; ++k) {
            ull w = __ldg(&wrow[k << 6]);
            fma2(acc[k][0], w, p0);
            fma2(acc[k][1], w, p1);
            fma2(acc[k][2], w, p2);
            fma2(acc[k][3], w, p3);
        }
    }

    #pragma unroll 1
    for (int k = 0; k < 8; ++k) {
        int co = co0 + k;
        float bv = g_B1[co];
        size_t gb = nb + ((size_t)co << CH_SHIFT) + pb + px0;
        float4 xa = *(const float4*)&x[gb];
        float4 xb = *(const float4*)&x[gb + 4];
        float o[8];
        #pragma unroll
        for (int j = 0; j < 4; ++j) {
            float lo, hi; unpk2(acc[k][j], lo, hi);
            o[2*j] = lo + bv; o[2*j+1] = hi + bv;
        }
        float4 ra = make_float4(xa.x*o[0], xa.y*o[1], xa.z*o[2], xa.w*o[3]);
        float4 rb = make_float4(xb.x*o[4], xb.y*o[5], xb.z*o[6], xb.w*o[7]);
        *(float4*)&out[gb]     = ra;
        *(float4*)&out[gb + 4] = rb;
    }
}

// ---------------------------------------------------------------------------
extern "C" void kernel_launch(void* const* d_in, const int* in_sizes, int n_in,
                              void* d_out, int out_size) {
    const float *x = 0, *w0 = 0, *ws = 0, *w1 = 0;
    const float* small[5] = {0, 0, 0, 0, 0};
    int ns = 0;
    for (int i = 0; i < n_in; ++i) {
        const float* p = (const float*)d_in[i];
        switch (in_sizes[i]) {
            case TOTAL:  x  = p; break;
            case 8000:   w0 = p; break;
            case 21952:  ws = p; break;
            case 4096:   w1 = p; break;
            case 64:     if (ns < 5) small[ns++] = p; break;
            default: break;
        }
    }
    if (!x || !w0 || !ws || !w1 || ns != 5) {
        x = (const float*)d_in[0];
        small[0] = (const float*)d_in[1];
        small[1] = (const float*)d_in[2];
        w0 = (const float*)d_in[3];
        small[2] = (const float*)d_in[4];
        ws = (const float*)d_in[5];
        small[3] = (const float*)d_in[6];
        w1 = (const float*)d_in[7];
        small[4] = (const float*)d_in[8];
    }
    float* out = (float*)d_out;

    cudaFuncSetAttribute(k3_conv7, cudaFuncAttributeMaxDynamicSharedMemorySize, K3_SMEM_BYTES);
    cudaFuncSetAttribute(k4_point, cudaFuncAttributeMaxDynamicSharedMemorySize, K4_SMEM_BYTES);

    k1_stats<<<dim3(64, 64), 256>>>(x);
    k1_final<<<1, 64>>>(small[0], small[1], small[2], small[3], small[4], w0);
    k4_packw<<<16, 256>>>(w1);
    k2_conv5<<<dim3(64, 64, 2), 256>>>(x, w0);
    k3_conv7<<<dim3(54, 64, 2), 256, K3_SMEM_BYTES>>>(ws);
    k4_point<<<dim3(1024, 2), 256, K4_SMEM_BYTES>>>(x, out);
}